// round 15
// baseline (speedup 1.0000x reference)
#include <cuda_runtime.h>
#include <cuda_fp16.h>
#include <math.h>
#include <stdint.h>

#define N_TOK 4096
#define DIM   1024
#define HID   4096
#define NEXP  8
#define CAP   1280   // int(1.25 * 4096 * 2 / 8)

// ---------------- scratch (static device globals; no allocation) ----------------
// A'-fragment-major (fp16): k16-block = m16 x k16 = 128 u32 words.
// B'-fragment-major (fp16): k32-block = k32 x n8 = 128 u32 words.
__device__ uint32_t g_xbuf[(size_t)NEXP * CAP * DIM / 2];
__device__ uint32_t g_h   [(size_t)NEXP * CAP * HID / 2];
__device__ uint32_t g_wr1 [(size_t)NEXP * DIM * HID / 2];
__device__ uint32_t g_wr2 [(size_t)NEXP * HID * DIM / 2];
__device__ int      g_expid[2 * N_TOK];
__device__ int      g_slot [2 * N_TOK];
__device__ int      g_rev  [NEXP * CAP];     // (e,slot) -> assignment idx or -1
__device__ float    g_wtp  [2 * N_TOK];

__device__ __forceinline__ uint32_t smem_to_u32(const void* p) {
    uint32_t a;
    asm("{ .reg .u64 t; cvta.to.shared.u64 t, %1; cvt.u32.u64 %0, t; }" : "=r"(a) : "l"(p));
    return a;
}
#define CP_ASYNC16(dst, src) \
    asm volatile("cp.async.cg.shared.global [%0], [%1], 16;\n" :: "r"(dst), "l"(src))
#define CP_COMMIT() asm volatile("cp.async.commit_group;\n" ::: "memory")
#define CP_WAIT0()  asm volatile("cp.async.wait_group 0;\n" ::: "memory")

__device__ __forceinline__ void mma16(float d[4], const uint4& a, uint32_t b0, uint32_t b1) {
    asm volatile(
        "mma.sync.aligned.m16n8k16.row.col.f32.f16.f16.f32 "
        "{%0,%1,%2,%3},{%4,%5,%6,%7},{%8,%9},{%0,%1,%2,%3};"
        : "+f"(d[0]), "+f"(d[1]), "+f"(d[2]), "+f"(d[3])
        : "r"(a.x), "r"(a.y), "r"(a.z), "r"(a.w), "r"(b0), "r"(b1));
}

// ---------------- one permute strip: W[K,N] k32 x n32 -> 4 B' k32-blocks ----------------
__device__ __forceinline__ void permute_strip(const float* __restrict__ W,
                                              uint32_t* __restrict__ R,
                                              int K, int N, int strip, int lane,
                                              float (*s)[36]) {
    int spe = (K >> 5) * (N >> 5);
    int e = strip / spe;
    int st = strip - e * spe;
    int n32 = st / (K >> 5);
    int k32 = st - n32 * (K >> 5);
    const float* Wp = W + (size_t)e * K * N + (size_t)(k32 * 32) * N + n32 * 32;
#pragma unroll
    for (int i = 0; i < 8; i++) {
        int idx = i * 32 + lane;
        int row = idx >> 3, c4 = (idx & 7) * 4;
        float4 v = *(const float4*)(Wp + (size_t)row * N + c4);
        s[row][c4 + 0] = v.x; s[row][c4 + 1] = v.y;
        s[row][c4 + 2] = v.z; s[row][c4 + 3] = v.w;
    }
    __syncwarp();
    int grp = lane >> 2, qd = lane & 3;
    uint32_t* Re = R + (size_t)e * ((size_t)(K >> 5) * (N >> 3)) * 128;
#pragma unroll
    for (int b = 0; b < 4; b++) {
        int n = b * 8 + grp;
        __half2 h0 = __floats2half2_rn(s[2 * qd][n],      s[2 * qd + 1][n]);
        __half2 h1 = __floats2half2_rn(s[2 * qd + 8][n],  s[2 * qd + 9][n]);
        __half2 h2 = __floats2half2_rn(s[2 * qd + 16][n], s[2 * qd + 17][n]);
        __half2 h3 = __floats2half2_rn(s[2 * qd + 24][n], s[2 * qd + 25][n]);
        uint4 o;
        o.x = *(uint32_t*)&h0; o.y = *(uint32_t*)&h1;
        o.z = *(uint32_t*)&h2; o.w = *(uint32_t*)&h3;
        size_t blk = (size_t)(n32 * 4 + b) * (K >> 5) + k32;
        *(uint4*)(Re + blk * 128 + lane * 4) = o;
    }
    __syncwarp();
}

// ---------------- router ----------------
__global__ void router_kernel(const float* __restrict__ x,
                              const float* __restrict__ gw,
                              int* __restrict__ expid,
                              float* __restrict__ wt) {
    int warp = threadIdx.x >> 5, lane = threadIdx.x & 31;
    int t = blockIdx.x * 8 + warp;
    if (t >= N_TOK) return;
    const float* xr = x + (size_t)t * DIM;
    float acc[8] = {0.f,0.f,0.f,0.f,0.f,0.f,0.f,0.f};
    for (int d = lane; d < DIM; d += 32) {
        float xv = xr[d];
        const float4* g4 = (const float4*)(gw + (size_t)d * NEXP);
        float4 a = g4[0], b = g4[1];
        acc[0] += xv * a.x; acc[1] += xv * a.y; acc[2] += xv * a.z; acc[3] += xv * a.w;
        acc[4] += xv * b.x; acc[5] += xv * b.y; acc[6] += xv * b.z; acc[7] += xv * b.w;
    }
#pragma unroll
    for (int e = 0; e < 8; e++)
#pragma unroll
        for (int o = 16; o; o >>= 1) acc[e] += __shfl_xor_sync(0xffffffffu, acc[e], o);
    if (lane == 0) {
        int i0 = 0; float l0 = acc[0];
#pragma unroll
        for (int e = 1; e < 8; e++) if (acc[e] > l0) { l0 = acc[e]; i0 = e; }
        int i1 = -1; float l1 = -INFINITY;
#pragma unroll
        for (int e = 0; e < 8; e++) if (e != i0 && acc[e] > l1) { l1 = acc[e]; i1 = e; }
        float z  = expf(l1 - l0);
        float p0 = 1.0f / (1.0f + z);
        expid[t]         = i0;
        expid[N_TOK + t] = i1;
        wt[t]            = p0;
        wt[N_TOK + t]    = z * p0;
    }
}

// ---------------- fused: block 0 = slot assignment + reverse map; blocks >=1 = permute1 ----------------
__global__ void assign_perm_kernel(const int* __restrict__ expid, int* __restrict__ slot,
                                   int* __restrict__ rev,
                                   const float* __restrict__ W, uint32_t* __restrict__ R,
                                   int K, int N) {
    __shared__ float sperm[8][32][36];
    int tid = threadIdx.x, lane = tid & 31, warp = tid >> 5;

    if (blockIdx.x > 0) {
        int strip = (int)(blockIdx.x - 1) * 8 + warp;
        permute_strip(W, R, K, N, strip, lane, sperm[warp]);
        return;
    }

    __shared__ int counters[NEXP];
    __shared__ int warp_hist[8][NEXP];
    for (int i = tid; i < NEXP * CAP; i += 256) rev[i] = -1;
    if (tid < NEXP) counters[tid] = 0;
    __syncthreads();
    for (int a = 0; a < 2 * N_TOK; a += 256) {
        int idx = a + tid;
        int e = expid[idx];
        unsigned peers = __match_any_sync(0xffffffffu, e);
        int rank = __popc(peers & ((1u << lane) - 1u));
        if (tid < 64) ((int*)warp_hist)[tid] = 0;
        __syncthreads();
        if (rank == 0) warp_hist[warp][e] = __popc(peers);
        __syncthreads();
        int base = counters[e];
#pragma unroll
        for (int w = 0; w < 8; w++) if (w < warp) base += warp_hist[w][e];
        int s = base + rank;
        if (s < CAP) {
            slot[idx] = s;
            rev[e * CAP + s] = idx;
        } else {
            slot[idx] = -1;
        }
        __syncthreads();
        if (tid < NEXP) {
            int c = counters[tid];
#pragma unroll
            for (int w = 0; w < 8; w++) c += warp_hist[w][tid];
            counters[tid] = c;
        }
        __syncthreads();
    }
}

// ---------------- gather: x row -> A'-fragment fp16 ----------------
__global__ void gather_kernel(const float* __restrict__ x,
                              const int* __restrict__ expid,
                              const int* __restrict__ slot,
                              uint32_t* __restrict__ xbuf) {
    int a = blockIdx.x;
    int s = slot[a];
    if (s < 0) return;
    int e = expid[a];
    int t = a & (N_TOK - 1);
    int tid = threadIdx.x;
    float4 v = ((const float4*)(x + (size_t)t * DIM))[tid];
    int r = s & 15;
    __half2 h0 = __floats2half2_rn(v.x, v.y);
    __half2 h1 = __floats2half2_rn(v.z, v.w);
    uint32_t* base = xbuf + (size_t)e * (CAP * DIM / 2)
                   + ((size_t)(s >> 4) * (DIM >> 4) + (tid >> 2)) * 128
                   + ((r & 7) * 4 + 2 * (tid & 1)) * 4 + (r >> 3) + 2 * ((tid >> 1) & 1);
    base[0] = *(uint32_t*)&h0;
    base[4] = *(uint32_t*)&h1;
}

// ============ fp16 mma.sync GEMM: k64 double-buffered stages, persistent CTAs ============
// Block tile 128x128, stage = k64 (A 16KB + B 16KB = 32KB), 2 stages, 8 warps of 64x32.
// ONE __syncthreads per k64: wait0 -> bar -> prefetch(kt+1) -> compute(kt).
#define STAGE_W 8192     // u32 words per stage (32KB)
#define SMEM_W  (2 * STAGE_W)   // 65536 B

template <bool AOUT>
__global__ void __launch_bounds__(256, 2)
gemm_fp16(const uint32_t* __restrict__ Ag, const uint32_t* __restrict__ Bg,
          const float* __restrict__ biasg, void* __restrict__ Cv,
          int ldc, long long sA, long long sB, long long sC, int sBias,
          int NK64, int NX, int NY,
          const float* __restrict__ PW, uint32_t* __restrict__ PR,
          int PK, int PN, int P,
          const int* __restrict__ rev, const float* __restrict__ wtv) {
    extern __shared__ __align__(16) uint32_t smemU[];
    const uint32_t sbase = smem_to_u32(smemU);

    const int tid = threadIdx.x, lane = tid & 31, wid = tid >> 5;
    const int wm16 = (wid & 1) * 4;
    const int wn = (wid >> 1) * 32;
    const int grp = lane >> 2, qd = lane & 3;
    // A loader: blkT = m16 block (0..7), laneT = lane; 4 x 16B chunks
    const int blkT = tid >> 5, laneT = tid & 31;
    // B loader: blkB = n8 block (0..15), inB (0..15); 4 x 16B chunks
    const int blkB = tid >> 4, inB = tid & 15;
    const uint32_t dstA = sbase + (uint32_t)(blkT * 2048 + laneT * 16);
    const uint32_t dstB = sbase + 16384u + (uint32_t)(blkB * 1024 + inB * 16);

    const int tpe = NX * NY;
    const int T = tpe * NEXP + P;      // total work items

    for (int widx = blockIdx.x; widx < T; widx += gridDim.x) {
        const int pa = (int)(((long long)widx * P) / T);
        const int pb = (int)(((long long)(widx + 1) * P) / T);

        if (pb > pa) {
            __syncthreads();   // previous item's smem use done
            float (*sp)[36] = reinterpret_cast<float(*)[36]>(smemU) + wid * 32;
            permute_strip(PW, PR, PK, PN, pa * 8 + wid, lane, sp);
            continue;
        }

        const int tile = widx - pa;
        const int e  = tile / tpe;
        const int r_ = tile - e * tpe;
        const int my = r_ / NX;
        const int nx = r_ - my * NX;
        const int m0 = my * 128, n0 = nx * 128;

        // A': m16-row stride = (4*NK64) k16-blocks * 128 words = NK64*512 words
        const uint32_t* srcA = Ag + (size_t)e * sA
                             + (size_t)((m0 >> 4) + blkT) * NK64 * 512 + laneT * 4;
        // B': n8-row stride = (2*NK64) k32-blocks * 128 words = NK64*256 words
        const uint32_t* srcB = Bg + (size_t)e * sB
                             + (size_t)((n0 >> 3) + blkB) * NK64 * 256 + inB * 4;
        const float* bias = biasg + (size_t)e * sBias;

#define CPAB(kt, st)                                                         \
    do {                                                                     \
        uint32_t da = dstA + (uint32_t)((st) * (STAGE_W * 4));               \
        const uint32_t* sa = srcA + (size_t)(kt) * 512;                      \
        CP_ASYNC16(da,        sa);                                           \
        CP_ASYNC16(da + 512,  sa + 128);                                     \
        CP_ASYNC16(da + 1024, sa + 256);                                     \
        CP_ASYNC16(da + 1536, sa + 384);                                     \
        uint32_t db = dstB + (uint32_t)((st) * (STAGE_W * 4));               \
        const uint32_t* sb_ = srcB + (size_t)(kt) * 256;                     \
        CP_ASYNC16(db,       sb_);                                           \
        CP_ASYNC16(db + 256, sb_ + 64);                                      \
        CP_ASYNC16(db + 512, sb_ + 128);                                     \
        CP_ASYNC16(db + 768, sb_ + 192);                                     \
    } while (0)

        float acc[4][4][4];
#pragma unroll
        for (int i = 0; i < 4; i++)
#pragma unroll
            for (int j = 0; j < 4; j++)
#pragma unroll
                for (int r2 = 0; r2 < 4; r2++) acc[i][j][r2] = 0.f;

#define COMPUTE(st)                                                          \
    do {                                                                     \
        const uint32_t* aS = smemU + (st) * STAGE_W;                         \
        const uint32_t* bS = aS + 4096;                                      \
        _Pragma("unroll") for (int k32 = 0; k32 < 2; k32++) {                \
            uint4 b[4];                                                      \
            _Pragma("unroll") for (int nt = 0; nt < 4; nt++)                 \
                b[nt] = *(const uint4*)(bS + ((wn >> 3) + nt) * 256 +        \
                                        k32 * 128 + lane * 4);               \
            _Pragma("unroll") for (int ks = 0; ks < 2; ks++) {               \
                uint4 a[4];                                                  \
                _Pragma("unroll") for (int mt = 0; mt < 4; mt++)             \
                    a[mt] = *(const uint4*)(aS + (wm16 + mt) * 512 +         \
                                            (k32 * 2 + ks) * 128 + lane * 4);\
                _Pragma("unroll") for (int mt = 0; mt < 4; mt++)             \
                    _Pragma("unroll") for (int nt = 0; nt < 4; nt++)         \
                        mma16(acc[mt][nt], a[mt],                            \
                              ks ? b[nt].z : b[nt].x,                        \
                              ks ? b[nt].w : b[nt].y);                       \
            }                                                                \
        }                                                                    \
    } while (0)

// one barrier per k64 stage; prefetch next stage issued right after the barrier
#define ITER(kt, st)                                                         \
    do {                                                                     \
        CP_WAIT0();                                                          \
        __syncthreads();                                                     \
        if ((kt) + 1 < NK64) CPAB((kt) + 1, (st) ^ 1);                       \
        CP_COMMIT();                                                         \
        COMPUTE(st);                                                         \
    } while (0)

        __syncthreads();   // previous item's smem use done
        CPAB(0, 0); CP_COMMIT();

        for (int kt2 = 0; kt2 < NK64; kt2 += 2) {
            ITER(kt2 + 0, 0);
            ITER(kt2 + 1, 1);
        }
#undef CPAB
#undef COMPUTE
#undef ITER

        // ---- epilogue ----
        if (AOUT) {
            // GELU + fp16 A'-layout store (input to GEMM2)
#pragma unroll
            for (int mt = 0; mt < 4; mt++) {
#pragma unroll
                for (int nt = 0; nt < 4; nt++) {
                    int col = n0 + wn + nt * 8 + qd * 2;
                    float b0 = bias[col], b1 = bias[col + 1];
#pragma unroll
                    for (int h = 0; h < 2; h++) {
                        float v0 = acc[mt][nt][h * 2 + 0] + b0;
                        float v1 = acc[mt][nt][h * 2 + 1] + b1;
                        v0 = 0.5f * v0 * (1.0f + erff(v0 * 0.70710678118654752f));
                        v1 = 0.5f * v1 * (1.0f + erff(v1 * 0.70710678118654752f));
                        size_t row16 = (size_t)((m0 >> 4) + wm16 + mt);
                        int col16 = ((n0 + wn) >> 4) + (nt >> 1);
                        uint32_t* cw = (uint32_t*)Cv + (size_t)e * sC
                                     + (row16 * (ldc >> 4) + col16) * 128
                                     + lane * 4 + 2 * (nt & 1);
                        __half2 hv = __floats2half2_rn(v0, v1);
                        cw[h] = *(uint32_t*)&hv;
                    }
                }
            }
        } else {
            // fused combine: scatter w*(acc+bias) into out via atomicAdd
            float* outp = (float*)Cv;
#pragma unroll
            for (int mt = 0; mt < 4; mt++) {
#pragma unroll
                for (int h = 0; h < 2; h++) {
                    int mrow = m0 + (wm16 << 4) + mt * 16 + grp + h * 8;
                    int idx = rev[e * CAP + mrow];
                    if (idx < 0) continue;
                    float w = wtv[idx];
                    float* op = outp + (size_t)(idx & (N_TOK - 1)) * ldc;
#pragma unroll
                    for (int nt = 0; nt < 4; nt++) {
                        int col = n0 + wn + nt * 8 + qd * 2;
                        float v0 = w * (acc[mt][nt][h * 2 + 0] + bias[col]);
                        float v1 = w * (acc[mt][nt][h * 2 + 1] + bias[col + 1]);
                        atomicAdd(op + col,     v0);
                        atomicAdd(op + col + 1, v1);
                    }
                }
            }
        }
    }
}

// ---------------- launch ----------------
extern "C" void kernel_launch(void* const* d_in, const int* in_sizes, int n_in,
                              void* d_out, int out_size) {
    const float* x         = (const float*)d_in[0];
    const float* gate_w    = (const float*)d_in[1];
    const float* c_fc      = (const float*)d_in[2];
    const float* fc_bias   = (const float*)d_in[3];
    const float* c_proj    = (const float*)d_in[4];
    const float* proj_bias = (const float*)d_in[5];
    float* out = (float*)d_out;

    uint32_t *xbuf, *hbuf, *wr1, *wr2;
    float *wt;
    int *expid, *slot, *rev;
    cudaGetSymbolAddress((void**)&xbuf,  g_xbuf);
    cudaGetSymbolAddress((void**)&hbuf,  g_h);
    cudaGetSymbolAddress((void**)&wr1,   g_wr1);
    cudaGetSymbolAddress((void**)&wr2,   g_wr2);
    cudaGetSymbolAddress((void**)&expid, g_expid);
    cudaGetSymbolAddress((void**)&slot,  g_slot);
    cudaGetSymbolAddress((void**)&rev,   g_rev);
    cudaGetSymbolAddress((void**)&wt,    g_wtp);

    int nsm = 148;
    cudaDeviceGetAttribute(&nsm, cudaDevAttrMultiProcessorCount, 0);
    const int pgrid = 2 * nsm;

    const int smem_bytes = SMEM_W * 4;
    cudaFuncSetAttribute(gemm_fp16<true>,  cudaFuncAttributeMaxDynamicSharedMemorySize, smem_bytes);
    cudaFuncSetAttribute(gemm_fp16<false>, cudaFuncAttributeMaxDynamicSharedMemorySize, smem_bytes);

    // zero-init output (fused-combine accumulates into it)
    cudaMemsetAsync(d_out, 0, (size_t)out_size * sizeof(float), 0);

    router_kernel<<<N_TOK / 8, 256>>>(x, gate_w, expid, wt);

    // assign + reverse map (block 0) + permute1 c_fc -> wr1 (blocks 1..4096)
    const int p1units = (NEXP * (DIM / 32) * (HID / 32)) / 8;   // 4096
    assign_perm_kernel<<<1 + p1units, 256>>>(expid, slot, rev, c_fc, wr1, DIM, HID);

    gather_kernel<<<2 * N_TOK, 256>>>(x, expid, slot, xbuf);

    // GEMM1 + GELU (A'-out) with fused permute2 c_proj -> wr2 interleaved
    const int p2units = (NEXP * (HID / 32) * (DIM / 32)) / 8;   // 4096
    gemm_fp16<true><<<pgrid, 256, smem_bytes>>>(xbuf, wr1, fc_bias, hbuf,
                                                HID,
                                                (long long)CAP * DIM / 2, (long long)DIM * HID / 2,
                                                (long long)CAP * HID / 2, HID,
                                                DIM / 64, HID / 128, CAP / 128,
                                                c_proj, wr2, HID, DIM, p2units,
                                                (const int*)nullptr, (const float*)nullptr);

    // GEMM2 + bias with fused combine (atomic scatter into out)
    gemm_fp16<false><<<pgrid, 256, smem_bytes>>>(hbuf, wr2, proj_bias, out,
                                                 DIM,
                                                 (long long)CAP * HID / 2, (long long)HID * DIM / 2,
                                                 0, DIM,
                                                 HID / 64, DIM / 128, CAP / 128,
                                                 (const float*)nullptr, (uint32_t*)nullptr,
                                                 0, 0, 0,
                                                 rev, wt);
}

// round 16
// speedup vs baseline: 1.0148x; 1.0148x over previous
#include <cuda_runtime.h>
#include <cuda_fp16.h>
#include <math.h>
#include <stdint.h>

#define N_TOK 4096
#define DIM   1024
#define HID   4096
#define NEXP  8
#define CAP   1280   // int(1.25 * 4096 * 2 / 8)

// ---------------- scratch (static device globals; no allocation) ----------------
// A'-fragment-major (fp16): k16-block = m16 x k16 = 128 u32 words.
// B'-fragment-major (fp16): k32-block = k32 x n8 = 128 u32 words.
__device__ uint32_t g_xbuf[(size_t)NEXP * CAP * DIM / 2];
__device__ uint32_t g_h   [(size_t)NEXP * CAP * HID / 2];
__device__ float    g_eout[(size_t)NEXP * CAP * DIM];
__device__ uint32_t g_wr1 [(size_t)NEXP * DIM * HID / 2];
__device__ uint32_t g_wr2 [(size_t)NEXP * HID * DIM / 2];
__device__ int      g_expid[2 * N_TOK];
__device__ int      g_slot [2 * N_TOK];
__device__ int      g_hist [32 * NEXP];     // per-256-token-block expert histograms
__device__ float    g_wtp  [2 * N_TOK];

__device__ __forceinline__ uint32_t smem_to_u32(const void* p) {
    uint32_t a;
    asm("{ .reg .u64 t; cvta.to.shared.u64 t, %1; cvt.u32.u64 %0, t; }" : "=r"(a) : "l"(p));
    return a;
}
#define CP_ASYNC16(dst, src) \
    asm volatile("cp.async.cg.shared.global [%0], [%1], 16;\n" :: "r"(dst), "l"(src))
#define CP_COMMIT() asm volatile("cp.async.commit_group;\n" ::: "memory")
#define CP_WAIT2()  asm volatile("cp.async.wait_group 2;\n" ::: "memory")

__device__ __forceinline__ void mma16(float d[4], const uint4& a, uint32_t b0, uint32_t b1) {
    asm volatile(
        "mma.sync.aligned.m16n8k16.row.col.f32.f16.f16.f32 "
        "{%0,%1,%2,%3},{%4,%5,%6,%7},{%8,%9},{%0,%1,%2,%3};"
        : "+f"(d[0]), "+f"(d[1]), "+f"(d[2]), "+f"(d[3])
        : "r"(a.x), "r"(a.y), "r"(a.z), "r"(a.w), "r"(b0), "r"(b1));
}

// ---------------- one permute strip: W[K,N] k32 x n32 -> 4 B' k32-blocks ----------------
__device__ __forceinline__ void permute_strip(const float* __restrict__ W,
                                              uint32_t* __restrict__ R,
                                              int K, int N, int strip, int lane,
                                              float (*s)[36]) {
    int spe = (K >> 5) * (N >> 5);
    int e = strip / spe;
    int st = strip - e * spe;
    int n32 = st / (K >> 5);
    int k32 = st - n32 * (K >> 5);
    const float* Wp = W + (size_t)e * K * N + (size_t)(k32 * 32) * N + n32 * 32;
#pragma unroll
    for (int i = 0; i < 8; i++) {
        int idx = i * 32 + lane;
        int row = idx >> 3, c4 = (idx & 7) * 4;
        float4 v = *(const float4*)(Wp + (size_t)row * N + c4);
        s[row][c4 + 0] = v.x; s[row][c4 + 1] = v.y;
        s[row][c4 + 2] = v.z; s[row][c4 + 3] = v.w;
    }
    __syncwarp();
    int grp = lane >> 2, qd = lane & 3;
    uint32_t* Re = R + (size_t)e * ((size_t)(K >> 5) * (N >> 3)) * 128;
#pragma unroll
    for (int b = 0; b < 4; b++) {
        int n = b * 8 + grp;
        __half2 h0 = __floats2half2_rn(s[2 * qd][n],      s[2 * qd + 1][n]);
        __half2 h1 = __floats2half2_rn(s[2 * qd + 8][n],  s[2 * qd + 9][n]);
        __half2 h2 = __floats2half2_rn(s[2 * qd + 16][n], s[2 * qd + 17][n]);
        __half2 h3 = __floats2half2_rn(s[2 * qd + 24][n], s[2 * qd + 25][n]);
        uint4 o;
        o.x = *(uint32_t*)&h0; o.y = *(uint32_t*)&h1;
        o.z = *(uint32_t*)&h2; o.w = *(uint32_t*)&h3;
        size_t blk = (size_t)(n32 * 4 + b) * (K >> 5) + k32;
        *(uint4*)(Re + blk * 128 + lane * 4) = o;
    }
    __syncwarp();
}

// ---------------- router ----------------
__global__ void router_kernel(const float* __restrict__ x,
                              const float* __restrict__ gw,
                              int* __restrict__ expid,
                              float* __restrict__ wt) {
    int warp = threadIdx.x >> 5, lane = threadIdx.x & 31;
    int t = blockIdx.x * 8 + warp;
    if (t >= N_TOK) return;
    const float* xr = x + (size_t)t * DIM;
    float acc[8] = {0.f,0.f,0.f,0.f,0.f,0.f,0.f,0.f};
    for (int d = lane; d < DIM; d += 32) {
        float xv = xr[d];
        const float4* g4 = (const float4*)(gw + (size_t)d * NEXP);
        float4 a = g4[0], b = g4[1];
        acc[0] += xv * a.x; acc[1] += xv * a.y; acc[2] += xv * a.z; acc[3] += xv * a.w;
        acc[4] += xv * b.x; acc[5] += xv * b.y; acc[6] += xv * b.z; acc[7] += xv * b.w;
    }
#pragma unroll
    for (int e = 0; e < 8; e++)
#pragma unroll
        for (int o = 16; o; o >>= 1) acc[e] += __shfl_xor_sync(0xffffffffu, acc[e], o);
    if (lane == 0) {
        int i0 = 0; float l0 = acc[0];
#pragma unroll
        for (int e = 1; e < 8; e++) if (acc[e] > l0) { l0 = acc[e]; i0 = e; }
        int i1 = -1; float l1 = -INFINITY;
#pragma unroll
        for (int e = 0; e < 8; e++) if (e != i0 && acc[e] > l1) { l1 = acc[e]; i1 = e; }
        float z  = expf(l1 - l0);
        float p0 = 1.0f / (1.0f + z);
        expid[t]         = i0;
        expid[N_TOK + t] = i1;
        wt[t]            = p0;
        wt[N_TOK + t]    = z * p0;
    }
}

// ---------------- K1: per-block expert histograms (blocks 0..31) + permute1 (blocks 32+) ----------------
__global__ void hist_perm_kernel(const int* __restrict__ expid, int* __restrict__ hist,
                                 const float* __restrict__ W, uint32_t* __restrict__ R,
                                 int K, int N) {
    __shared__ float sperm[8][32][36];
    int tid = threadIdx.x, lane = tid & 31, warp = tid >> 5;

    if (blockIdx.x >= 32) {
        int strip = (int)(blockIdx.x - 32) * 8 + warp;
        permute_strip(W, R, K, N, strip, lane, sperm[warp]);
        return;
    }

    __shared__ int warp_hist[8][NEXP];
    if (tid < 64) ((int*)warp_hist)[tid] = 0;
    __syncthreads();
    int idx = blockIdx.x * 256 + tid;
    int e = expid[idx];
    unsigned peers = __match_any_sync(0xffffffffu, e);
    int rank = __popc(peers & ((1u << lane) - 1u));
    if (rank == 0) warp_hist[warp][e] = __popc(peers);
    __syncthreads();
    if (tid < NEXP) {
        int c = 0;
#pragma unroll
        for (int w = 0; w < 8; w++) c += warp_hist[w][tid];
        hist[blockIdx.x * NEXP + tid] = c;
    }
}

// ---------------- K2: slots from global prefix + local rank (serial-equivalent) ----------------
__global__ void slot_kernel(const int* __restrict__ expid, const int* __restrict__ hist,
                            int* __restrict__ slot) {
    __shared__ int warp_hist[8][NEXP];
    __shared__ int gbase[NEXP];
    int tid = threadIdx.x, lane = tid & 31, warp = tid >> 5;
    if (tid < 64) ((int*)warp_hist)[tid] = 0;
    if (tid < NEXP) {
        int b = 0;
        for (int bb = 0; bb < (int)blockIdx.x; bb++) b += hist[bb * NEXP + tid];
        gbase[tid] = b;
    }
    __syncthreads();
    int idx = blockIdx.x * 256 + tid;
    int e = expid[idx];
    unsigned peers = __match_any_sync(0xffffffffu, e);
    int rank = __popc(peers & ((1u << lane) - 1u));
    if (rank == 0) warp_hist[warp][e] = __popc(peers);
    __syncthreads();
    int base = gbase[e];
#pragma unroll
    for (int w = 0; w < 8; w++) if (w < warp) base += warp_hist[w][e];
    int s = base + rank;
    slot[idx] = (s < CAP) ? s : -1;
}

// ---------------- gather: x row -> A'-fragment fp16 ----------------
__global__ void gather_kernel(const float* __restrict__ x,
                              const int* __restrict__ expid,
                              const int* __restrict__ slot,
                              uint32_t* __restrict__ xbuf) {
    int a = blockIdx.x;
    int s = slot[a];
    if (s < 0) return;
    int e = expid[a];
    int t = a & (N_TOK - 1);
    int tid = threadIdx.x;
    float4 v = ((const float4*)(x + (size_t)t * DIM))[tid];
    int r = s & 15;
    __half2 h0 = __floats2half2_rn(v.x, v.y);
    __half2 h1 = __floats2half2_rn(v.z, v.w);
    uint32_t* base = xbuf + (size_t)e * (CAP * DIM / 2)
                   + ((size_t)(s >> 4) * (DIM >> 4) + (tid >> 2)) * 128
                   + ((r & 7) * 4 + 2 * (tid & 1)) * 4 + (r >> 3) + 2 * ((tid >> 1) & 1);
    base[0] = *(uint32_t*)&h0;
    base[4] = *(uint32_t*)&h1;
}

// ============ fp16 mma.sync GEMM: k32 stages, persistent CTAs, optional fused permute ============
// Block tile 128x128, stage = k32, 8 warps of 64x32, 4-stage cp.async.
#define A_STAGE_W 2048   // u32 words (8KB)
#define B_STAGE_W 2048
#define SMEM_W    (4 * (A_STAGE_W + B_STAGE_W))   // 65536 B

template <bool AOUT>
__global__ void __launch_bounds__(256, 2)
gemm_fp16(const uint32_t* __restrict__ Ag, const uint32_t* __restrict__ Bg,
          const float* __restrict__ biasg, void* __restrict__ Cv,
          int ldc, long long sA, long long sB, long long sC, int sBias,
          int NK32, int NX, int NY,
          const float* __restrict__ PW, uint32_t* __restrict__ PR,
          int PK, int PN, int P) {
    extern __shared__ __align__(16) uint32_t smemU[];
    const uint32_t sbase = smem_to_u32(smemU);

    const int tid = threadIdx.x, lane = tid & 31, wid = tid >> 5;
    const int wm16 = (wid & 1) * 4;
    const int wn = (wid >> 1) * 32;
    const int grp = lane >> 2, qd = lane & 3;
    const int blkT = tid >> 5, laneT = tid & 31;       // A: m16 block, 16B chunk
    const int blkB = tid >> 4, fB = (tid & 15) * 8;    // B: n8 block, 8-word chunk
    const uint32_t dstA = sbase + (uint32_t)(blkT * 1024 + laneT * 16);
    const uint32_t dstB = sbase + (uint32_t)(4 * A_STAGE_W * 4) + (uint32_t)(blkB * 512 + fB * 4);

    const int tpe = NX * NY;
    const int T = tpe * NEXP + P;      // total work items

    for (int widx = blockIdx.x; widx < T; widx += gridDim.x) {
        const int pa = (int)(((long long)widx * P) / T);
        const int pb = (int)(((long long)(widx + 1) * P) / T);

        if (pb > pa) {
            __syncthreads();   // previous item's smem use done
            float (*sp)[36] = reinterpret_cast<float(*)[36]>(smemU) + wid * 32;
            permute_strip(PW, PR, PK, PN, pa * 8 + wid, lane, sp);
            continue;
        }

        const int tile = widx - pa;
        const int e  = tile / tpe;
        const int r_ = tile - e * tpe;
        const int my = r_ / NX;
        const int nx = r_ - my * NX;
        const int m0 = my * 128, n0 = nx * 128;

        const uint32_t* srcA = Ag + (size_t)e * sA
                             + ((size_t)((m0 >> 4) + blkT) * (2 * NK32)) * 128 + laneT * 4;
        const uint32_t* srcB = Bg + (size_t)e * sB
                             + ((size_t)((n0 >> 3) + blkB) * NK32) * 128 + fB;
        const float* bias = biasg + (size_t)e * sBias;

#define CPAB(kt, st)                                                         \
    do {                                                                     \
        uint32_t da = dstA + (uint32_t)((st) * (A_STAGE_W * 4));             \
        const uint32_t* sa = srcA + (size_t)(kt) * 256;                      \
        CP_ASYNC16(da, sa);                                                  \
        CP_ASYNC16(da + 512, sa + 128);                                      \
        uint32_t db = dstB + (uint32_t)((st) * (B_STAGE_W * 4));             \
        const uint32_t* sb_ = srcB + (size_t)(kt) * 128;                     \
        CP_ASYNC16(db, sb_);                                                 \
        CP_ASYNC16(db + 16, sb_ + 4);                                        \
    } while (0)

        float acc[4][4][4];
#pragma unroll
        for (int i = 0; i < 4; i++)
#pragma unroll
            for (int j = 0; j < 4; j++)
#pragma unroll
                for (int r2 = 0; r2 < 4; r2++) acc[i][j][r2] = 0.f;

#define COMPUTE(st)                                                          \
    do {                                                                     \
        const uint32_t* aS = smemU + (st) * A_STAGE_W;                       \
        const uint32_t* bS = smemU + 4 * A_STAGE_W + (st) * B_STAGE_W;       \
        uint4 b[4];                                                          \
        _Pragma("unroll") for (int nt = 0; nt < 4; nt++)                     \
            b[nt] = *(const uint4*)(bS + ((wn >> 3) + nt) * 128 + lane * 4); \
        _Pragma("unroll") for (int ks = 0; ks < 2; ks++) {                   \
            uint4 a[4];                                                      \
            _Pragma("unroll") for (int mt = 0; mt < 4; mt++)                 \
                a[mt] = *(const uint4*)(aS + (wm16 + mt) * 256 + ks * 128 +  \
                                        lane * 4);                           \
            _Pragma("unroll") for (int mt = 0; mt < 4; mt++)                 \
                _Pragma("unroll") for (int nt = 0; nt < 4; nt++)             \
                    mma16(acc[mt][nt], a[mt],                                \
                          ks ? b[nt].z : b[nt].x, ks ? b[nt].w : b[nt].y);   \
        }                                                                    \
    } while (0)

#define ITER(kt, st)                                                         \
    do {                                                                     \
        CP_WAIT2();                                                          \
        __syncthreads();                                                     \
        COMPUTE(st);                                                         \
        if ((kt) + 3 < NK32) CPAB((kt) + 3, ((st) + 3) & 3);                 \
        CP_COMMIT();                                                         \
    } while (0)

        __syncthreads();   // previous item's smem use done
        CPAB(0, 0); CP_COMMIT();
        CPAB(1, 1); CP_COMMIT();
        CPAB(2, 2); CP_COMMIT();

        for (int kt4 = 0; kt4 < NK32; kt4 += 4) {
            ITER(kt4 + 0, 0);
            ITER(kt4 + 1, 1);
            ITER(kt4 + 2, 2);
            ITER(kt4 + 3, 3);
        }
#undef CPAB
#undef COMPUTE
#undef ITER

        // ---- epilogue ----
        if (AOUT) {
#pragma unroll
            for (int mt = 0; mt < 4; mt++) {
#pragma unroll
                for (int nt = 0; nt < 4; nt++) {
                    int col = n0 + wn + nt * 8 + qd * 2;
                    float b0 = bias[col], b1 = bias[col + 1];
#pragma unroll
                    for (int h = 0; h < 2; h++) {
                        float v0 = acc[mt][nt][h * 2 + 0] + b0;
                        float v1 = acc[mt][nt][h * 2 + 1] + b1;
                        v0 = 0.5f * v0 * (1.0f + erff(v0 * 0.70710678118654752f));
                        v1 = 0.5f * v1 * (1.0f + erff(v1 * 0.70710678118654752f));
                        size_t row16 = (size_t)((m0 >> 4) + wm16 + mt);
                        int col16 = ((n0 + wn) >> 4) + (nt >> 1);
                        uint32_t* cw = (uint32_t*)Cv + (size_t)e * sC
                                     + (row16 * (ldc >> 4) + col16) * 128
                                     + lane * 4 + 2 * (nt & 1);
                        __half2 hv = __floats2half2_rn(v0, v1);
                        cw[h] = *(uint32_t*)&hv;
                    }
                }
            }
        } else {
            float* C = (float*)Cv + (size_t)e * sC;
#pragma unroll
            for (int mt = 0; mt < 4; mt++) {
#pragma unroll
                for (int nt = 0; nt < 4; nt++) {
                    int col = n0 + wn + nt * 8 + qd * 2;
                    float b0 = bias[col], b1 = bias[col + 1];
#pragma unroll
                    for (int h = 0; h < 2; h++) {
                        float v0 = acc[mt][nt][h * 2 + 0] + b0;
                        float v1 = acc[mt][nt][h * 2 + 1] + b1;
                        size_t row = (size_t)(m0 + (wm16 << 4) + mt * 16 + grp + h * 8);
                        *(float2*)(C + row * ldc + col) = make_float2(v0, v1);
                    }
                }
            }
        }
    }
}

// ---------------- combine ----------------
__global__ void combine_kernel(const int* __restrict__ expid,
                               const int* __restrict__ slot,
                               const float* __restrict__ wt,
                               const float* __restrict__ eout,
                               float* __restrict__ out) {
    int t = blockIdx.x;
    int e0 = expid[t],          s0 = slot[t];          float w0 = wt[t];
    int e1 = expid[N_TOK + t],  s1 = slot[N_TOK + t];  float w1 = wt[N_TOK + t];
    int i = threadIdx.x;
    float4 r = make_float4(0.f, 0.f, 0.f, 0.f);
    if (s0 >= 0) {
        float4 v = ((const float4*)(eout + ((size_t)e0 * CAP + s0) * DIM))[i];
        r.x += w0 * v.x; r.y += w0 * v.y; r.z += w0 * v.z; r.w += w0 * v.w;
    }
    if (s1 >= 0) {
        float4 v = ((const float4*)(eout + ((size_t)e1 * CAP + s1) * DIM))[i];
        r.x += w1 * v.x; r.y += w1 * v.y; r.z += w1 * v.z; r.w += w1 * v.w;
    }
    ((float4*)(out + (size_t)t * DIM))[i] = r;
}

// ---------------- launch ----------------
extern "C" void kernel_launch(void* const* d_in, const int* in_sizes, int n_in,
                              void* d_out, int out_size) {
    const float* x         = (const float*)d_in[0];
    const float* gate_w    = (const float*)d_in[1];
    const float* c_fc      = (const float*)d_in[2];
    const float* fc_bias   = (const float*)d_in[3];
    const float* c_proj    = (const float*)d_in[4];
    const float* proj_bias = (const float*)d_in[5];
    float* out = (float*)d_out;

    uint32_t *xbuf, *hbuf, *wr1, *wr2;
    float *eout, *wt;
    int *expid, *slot, *hist;
    cudaGetSymbolAddress((void**)&xbuf,  g_xbuf);
    cudaGetSymbolAddress((void**)&hbuf,  g_h);
    cudaGetSymbolAddress((void**)&eout,  g_eout);
    cudaGetSymbolAddress((void**)&wr1,   g_wr1);
    cudaGetSymbolAddress((void**)&wr2,   g_wr2);
    cudaGetSymbolAddress((void**)&expid, g_expid);
    cudaGetSymbolAddress((void**)&slot,  g_slot);
    cudaGetSymbolAddress((void**)&hist,  g_hist);
    cudaGetSymbolAddress((void**)&wt,    g_wtp);

    int nsm = 148;
    cudaDeviceGetAttribute(&nsm, cudaDevAttrMultiProcessorCount, 0);
    const int pgrid = 2 * nsm;

    const int smem_bytes = SMEM_W * 4;
    cudaFuncSetAttribute(gemm_fp16<true>,  cudaFuncAttributeMaxDynamicSharedMemorySize, smem_bytes);
    cudaFuncSetAttribute(gemm_fp16<false>, cudaFuncAttributeMaxDynamicSharedMemorySize, smem_bytes);

    router_kernel<<<N_TOK / 8, 256>>>(x, gate_w, expid, wt);

    // K1: histograms (blocks 0..31) + permute1 c_fc -> wr1 (blocks 32..32+4095)
    const int p1units = (NEXP * (DIM / 32) * (HID / 32)) / 8;   // 4096
    hist_perm_kernel<<<32 + p1units, 256>>>(expid, hist, c_fc, wr1, DIM, HID);

    // K2: slots (serial-equivalent via global prefix)
    slot_kernel<<<32, 256>>>(expid, hist, slot);

    gather_kernel<<<2 * N_TOK, 256>>>(x, expid, slot, xbuf);

    // GEMM1 + GELU (A'-out) with fused permute2 c_proj -> wr2 interleaved
    const int p2units = (NEXP * (HID / 32) * (DIM / 32)) / 8;   // 4096
    gemm_fp16<true><<<pgrid, 256, smem_bytes>>>(xbuf, wr1, fc_bias, hbuf,
                                                HID,
                                                (long long)CAP * DIM / 2, (long long)DIM * HID / 2,
                                                (long long)CAP * HID / 2, HID,
                                                DIM / 32, HID / 128, CAP / 128,
                                                c_proj, wr2, HID, DIM, p2units);

    // GEMM2 + bias -> eout (fp32 row-major)
    gemm_fp16<false><<<pgrid, 256, smem_bytes>>>(hbuf, wr2, proj_bias, eout,
                                                 DIM,
                                                 (long long)CAP * HID / 2, (long long)HID * DIM / 2,
                                                 (long long)CAP * DIM, DIM,
                                                 HID / 32, DIM / 128, CAP / 128,
                                                 (const float*)nullptr, (uint32_t*)nullptr,
                                                 0, 0, 0);

    combine_kernel<<<N_TOK, 256>>>(expid, slot, wt, eout, out);
}

// round 17
// speedup vs baseline: 1.0159x; 1.0011x over previous
#include <cuda_runtime.h>
#include <cuda_fp16.h>
#include <math.h>
#include <stdint.h>

#define N_TOK 4096
#define DIM   1024
#define HID   4096
#define NEXP  8
#define CAP   1280   // int(1.25 * 4096 * 2 / 8)

// permute1 split across the three pre-GEMM kernels
#define P1_TOTAL   4096
#define P1_ROUTER  1365
#define P1_HIST    1365
#define P1_GATHER  (P1_TOTAL - P1_ROUTER - P1_HIST)

// ---------------- scratch (static device globals; no allocation) ----------------
__device__ uint32_t g_xbuf[(size_t)NEXP * CAP * DIM / 2];
__device__ uint32_t g_h   [(size_t)NEXP * CAP * HID / 2];
__device__ float    g_eout[(size_t)NEXP * CAP * DIM];
__device__ uint32_t g_wr1 [(size_t)NEXP * DIM * HID / 2];
__device__ uint32_t g_wr2 [(size_t)NEXP * HID * DIM / 2];
__device__ int      g_expid[2 * N_TOK];
__device__ int      g_slot [2 * N_TOK];
__device__ int      g_hist [32 * NEXP];
__device__ float    g_wtp  [2 * N_TOK];

__device__ __forceinline__ uint32_t smem_to_u32(const void* p) {
    uint32_t a;
    asm("{ .reg .u64 t; cvta.to.shared.u64 t, %1; cvt.u32.u64 %0, t; }" : "=r"(a) : "l"(p));
    return a;
}
#define CP_ASYNC16(dst, src) \
    asm volatile("cp.async.cg.shared.global [%0], [%1], 16;\n" :: "r"(dst), "l"(src))
#define CP_COMMIT() asm volatile("cp.async.commit_group;\n" ::: "memory")
#define CP_WAIT2()  asm volatile("cp.async.wait_group 2;\n" ::: "memory")

__device__ __forceinline__ void mma16(float d[4], const uint4& a, uint32_t b0, uint32_t b1) {
    asm volatile(
        "mma.sync.aligned.m16n8k16.row.col.f32.f16.f16.f32 "
        "{%0,%1,%2,%3},{%4,%5,%6,%7},{%8,%9},{%0,%1,%2,%3};"
        : "+f"(d[0]), "+f"(d[1]), "+f"(d[2]), "+f"(d[3])
        : "r"(a.x), "r"(a.y), "r"(a.z), "r"(a.w), "r"(b0), "r"(b1));
}

// ---------------- one permute strip: W[K,N] k32 x n32 -> 4 B' k32-blocks ----------------
__device__ __forceinline__ void permute_strip(const float* __restrict__ W,
                                              uint32_t* __restrict__ R,
                                              int K, int N, int strip, int lane,
                                              float (*s)[36]) {
    int spe = (K >> 5) * (N >> 5);
    int e = strip / spe;
    int st = strip - e * spe;
    int n32 = st / (K >> 5);
    int k32 = st - n32 * (K >> 5);
    const float* Wp = W + (size_t)e * K * N + (size_t)(k32 * 32) * N + n32 * 32;
#pragma unroll
    for (int i = 0; i < 8; i++) {
        int idx = i * 32 + lane;
        int row = idx >> 3, c4 = (idx & 7) * 4;
        float4 v = *(const float4*)(Wp + (size_t)row * N + c4);
        s[row][c4 + 0] = v.x; s[row][c4 + 1] = v.y;
        s[row][c4 + 2] = v.z; s[row][c4 + 3] = v.w;
    }
    __syncwarp();
    int grp = lane >> 2, qd = lane & 3;
    uint32_t* Re = R + (size_t)e * ((size_t)(K >> 5) * (N >> 3)) * 128;
#pragma unroll
    for (int b = 0; b < 4; b++) {
        int n = b * 8 + grp;
        __half2 h0 = __floats2half2_rn(s[2 * qd][n],      s[2 * qd + 1][n]);
        __half2 h1 = __floats2half2_rn(s[2 * qd + 8][n],  s[2 * qd + 9][n]);
        __half2 h2 = __floats2half2_rn(s[2 * qd + 16][n], s[2 * qd + 17][n]);
        __half2 h3 = __floats2half2_rn(s[2 * qd + 24][n], s[2 * qd + 25][n]);
        uint4 o;
        o.x = *(uint32_t*)&h0; o.y = *(uint32_t*)&h1;
        o.z = *(uint32_t*)&h2; o.w = *(uint32_t*)&h3;
        size_t blk = (size_t)(n32 * 4 + b) * (K >> 5) + k32;
        *(uint4*)(Re + blk * 128 + lane * 4) = o;
    }
    __syncwarp();
}

// ---------------- router (blocks < N_TOK/8) + permute1 share (blocks >=) ----------------
__global__ void router_kernel(const float* __restrict__ x,
                              const float* __restrict__ gw,
                              int* __restrict__ expid,
                              float* __restrict__ wt,
                              const float* __restrict__ PW, uint32_t* __restrict__ PR) {
    __shared__ float sperm[8][32][36];
    int warp = threadIdx.x >> 5, lane = threadIdx.x & 31;

    if (blockIdx.x >= N_TOK / 8) {
        int unit = (int)blockIdx.x - N_TOK / 8;
        permute_strip(PW, PR, DIM, HID, unit * 8 + warp, lane, sperm[warp]);
        return;
    }

    int t = blockIdx.x * 8 + warp;
    const float* xr = x + (size_t)t * DIM;
    float acc[8] = {0.f,0.f,0.f,0.f,0.f,0.f,0.f,0.f};
    for (int d = lane; d < DIM; d += 32) {
        float xv = xr[d];
        const float4* g4 = (const float4*)(gw + (size_t)d * NEXP);
        float4 a = g4[0], b = g4[1];
        acc[0] += xv * a.x; acc[1] += xv * a.y; acc[2] += xv * a.z; acc[3] += xv * a.w;
        acc[4] += xv * b.x; acc[5] += xv * b.y; acc[6] += xv * b.z; acc[7] += xv * b.w;
    }
#pragma unroll
    for (int e = 0; e < 8; e++)
#pragma unroll
        for (int o = 16; o; o >>= 1) acc[e] += __shfl_xor_sync(0xffffffffu, acc[e], o);
    if (lane == 0) {
        int i0 = 0; float l0 = acc[0];
#pragma unroll
        for (int e = 1; e < 8; e++) if (acc[e] > l0) { l0 = acc[e]; i0 = e; }
        int i1 = -1; float l1 = -INFINITY;
#pragma unroll
        for (int e = 0; e < 8; e++) if (e != i0 && acc[e] > l1) { l1 = acc[e]; i1 = e; }
        float z  = expf(l1 - l0);
        float p0 = 1.0f / (1.0f + z);
        expid[t]         = i0;
        expid[N_TOK + t] = i1;
        wt[t]            = p0;
        wt[N_TOK + t]    = z * p0;
    }
}

// ---------------- K1: histograms (blocks 0..31) + permute1 share (blocks 32+) ----------------
__global__ void hist_perm_kernel(const int* __restrict__ expid, int* __restrict__ hist,
                                 const float* __restrict__ PW, uint32_t* __restrict__ PR) {
    __shared__ float sperm[8][32][36];
    int tid = threadIdx.x, lane = tid & 31, warp = tid >> 5;

    if (blockIdx.x >= 32) {
        int unit = (int)blockIdx.x - 32 + P1_ROUTER;
        permute_strip(PW, PR, DIM, HID, unit * 8 + warp, lane, sperm[warp]);
        return;
    }

    __shared__ int warp_hist[8][NEXP];
    if (tid < 64) ((int*)warp_hist)[tid] = 0;
    __syncthreads();
    int idx = blockIdx.x * 256 + tid;
    int e = expid[idx];
    unsigned peers = __match_any_sync(0xffffffffu, e);
    int rank = __popc(peers & ((1u << lane) - 1u));
    if (rank == 0) warp_hist[warp][e] = __popc(peers);
    __syncthreads();
    if (tid < NEXP) {
        int c = 0;
#pragma unroll
        for (int w = 0; w < 8; w++) c += warp_hist[w][tid];
        hist[blockIdx.x * NEXP + tid] = c;
    }
}

// ---------------- K2: slots from global prefix + local rank ----------------
__global__ void slot_kernel(const int* __restrict__ expid, const int* __restrict__ hist,
                            int* __restrict__ slot) {
    __shared__ int warp_hist[8][NEXP];
    __shared__ int gbase[NEXP];
    int tid = threadIdx.x, lane = tid & 31, warp = tid >> 5;
    if (tid < 64) ((int*)warp_hist)[tid] = 0;
    if (tid < NEXP) {
        int b = 0;
        for (int bb = 0; bb < (int)blockIdx.x; bb++) b += hist[bb * NEXP + tid];
        gbase[tid] = b;
    }
    __syncthreads();
    int idx = blockIdx.x * 256 + tid;
    int e = expid[idx];
    unsigned peers = __match_any_sync(0xffffffffu, e);
    int rank = __popc(peers & ((1u << lane) - 1u));
    if (rank == 0) warp_hist[warp][e] = __popc(peers);
    __syncthreads();
    int base = gbase[e];
#pragma unroll
    for (int w = 0; w < 8; w++) if (w < warp) base += warp_hist[w][e];
    int s = base + rank;
    slot[idx] = (s < CAP) ? s : -1;
}

// ---------------- gather (blocks < 2*N_TOK) + permute1 share (blocks >=) ----------------
__global__ void gather_kernel(const float* __restrict__ x,
                              const int* __restrict__ expid,
                              const int* __restrict__ slot,
                              uint32_t* __restrict__ xbuf,
                              const float* __restrict__ PW, uint32_t* __restrict__ PR) {
    __shared__ float sperm[8][32][36];
    int tid = threadIdx.x, lane = tid & 31, warp = tid >> 5;

    if (blockIdx.x >= 2 * N_TOK) {
        int unit = (int)blockIdx.x - 2 * N_TOK + P1_ROUTER + P1_HIST;
        permute_strip(PW, PR, DIM, HID, unit * 8 + warp, lane, sperm[warp]);
        return;
    }

    int a = blockIdx.x;
    int s = slot[a];
    if (s < 0) return;
    int e = expid[a];
    int t = a & (N_TOK - 1);
    float4 v = ((const float4*)(x + (size_t)t * DIM))[tid];
    int r = s & 15;
    __half2 h0 = __floats2half2_rn(v.x, v.y);
    __half2 h1 = __floats2half2_rn(v.z, v.w);
    uint32_t* base = xbuf + (size_t)e * (CAP * DIM / 2)
                   + ((size_t)(s >> 4) * (DIM >> 4) + (tid >> 2)) * 128
                   + ((r & 7) * 4 + 2 * (tid & 1)) * 4 + (r >> 3) + 2 * ((tid >> 1) & 1);
    base[0] = *(uint32_t*)&h0;
    base[4] = *(uint32_t*)&h1;
}

// ============ fp16 mma.sync GEMM: k32 stages, persistent CTAs, optional fused permute ============
#define A_STAGE_W 2048   // u32 words (8KB)
#define B_STAGE_W 2048
#define SMEM_W    (4 * (A_STAGE_W + B_STAGE_W))   // 65536 B

template <bool AOUT>
__global__ void __launch_bounds__(256, 2)
gemm_fp16(const uint32_t* __restrict__ Ag, const uint32_t* __restrict__ Bg,
          const float* __restrict__ biasg, void* __restrict__ Cv,
          int ldc, long long sA, long long sB, long long sC, int sBias,
          int NK32, int NX, int NY,
          const float* __restrict__ PW, uint32_t* __restrict__ PR,
          int PK, int PN, int P) {
    extern __shared__ __align__(16) uint32_t smemU[];
    const uint32_t sbase = smem_to_u32(smemU);

    const int tid = threadIdx.x, lane = tid & 31, wid = tid >> 5;
    const int wm16 = (wid & 1) * 4;
    const int wn = (wid >> 1) * 32;
    const int grp = lane >> 2, qd = lane & 3;
    const int blkT = tid >> 5, laneT = tid & 31;
    const int blkB = tid >> 4, fB = (tid & 15) * 8;
    const uint32_t dstA = sbase + (uint32_t)(blkT * 1024 + laneT * 16);
    const uint32_t dstB = sbase + (uint32_t)(4 * A_STAGE_W * 4) + (uint32_t)(blkB * 512 + fB * 4);

    const int tpe = NX * NY;
    const int T = tpe * NEXP + P;

    for (int widx = blockIdx.x; widx < T; widx += gridDim.x) {
        const int pa = (int)(((long long)widx * P) / T);
        const int pb = (int)(((long long)(widx + 1) * P) / T);

        if (pb > pa) {
            __syncthreads();
            float (*sp)[36] = reinterpret_cast<float(*)[36]>(smemU) + wid * 32;
            permute_strip(PW, PR, PK, PN, pa * 8 + wid, lane, sp);
            continue;
        }

        const int tile = widx - pa;
        const int e  = tile / tpe;
        const int r_ = tile - e * tpe;
        const int my = r_ / NX;
        const int nx = r_ - my * NX;
        const int m0 = my * 128, n0 = nx * 128;

        const uint32_t* srcA = Ag + (size_t)e * sA
                             + ((size_t)((m0 >> 4) + blkT) * (2 * NK32)) * 128 + laneT * 4;
        const uint32_t* srcB = Bg + (size_t)e * sB
                             + ((size_t)((n0 >> 3) + blkB) * NK32) * 128 + fB;
        const float* bias = biasg + (size_t)e * sBias;

#define CPAB(kt, st)                                                         \
    do {                                                                     \
        uint32_t da = dstA + (uint32_t)((st) * (A_STAGE_W * 4));             \
        const uint32_t* sa = srcA + (size_t)(kt) * 256;                      \
        CP_ASYNC16(da, sa);                                                  \
        CP_ASYNC16(da + 512, sa + 128);                                      \
        uint32_t db = dstB + (uint32_t)((st) * (B_STAGE_W * 4));             \
        const uint32_t* sb_ = srcB + (size_t)(kt) * 128;                     \
        CP_ASYNC16(db, sb_);                                                 \
        CP_ASYNC16(db + 16, sb_ + 4);                                        \
    } while (0)

        float acc[4][4][4];
#pragma unroll
        for (int i = 0; i < 4; i++)
#pragma unroll
            for (int j = 0; j < 4; j++)
#pragma unroll
                for (int r2 = 0; r2 < 4; r2++) acc[i][j][r2] = 0.f;

#define COMPUTE(st)                                                          \
    do {                                                                     \
        const uint32_t* aS = smemU + (st) * A_STAGE_W;                       \
        const uint32_t* bS = smemU + 4 * A_STAGE_W + (st) * B_STAGE_W;       \
        uint4 b[4];                                                          \
        _Pragma("unroll") for (int nt = 0; nt < 4; nt++)                     \
            b[nt] = *(const uint4*)(bS + ((wn >> 3) + nt) * 128 + lane * 4); \
        _Pragma("unroll") for (int ks = 0; ks < 2; ks++) {                   \
            uint4 a[4];                                                      \
            _Pragma("unroll") for (int mt = 0; mt < 4; mt++)                 \
                a[mt] = *(const uint4*)(aS + (wm16 + mt) * 256 + ks * 128 +  \
                                        lane * 4);                           \
            _Pragma("unroll") for (int mt = 0; mt < 4; mt++)                 \
                _Pragma("unroll") for (int nt = 0; nt < 4; nt++)             \
                    mma16(acc[mt][nt], a[mt],                                \
                          ks ? b[nt].z : b[nt].x, ks ? b[nt].w : b[nt].y);   \
        }                                                                    \
    } while (0)

#define ITER(kt, st)                                                         \
    do {                                                                     \
        CP_WAIT2();                                                          \
        __syncthreads();                                                     \
        COMPUTE(st);                                                         \
        if ((kt) + 3 < NK32) CPAB((kt) + 3, ((st) + 3) & 3);                 \
        CP_COMMIT();                                                         \
    } while (0)

        __syncthreads();
        CPAB(0, 0); CP_COMMIT();
        CPAB(1, 1); CP_COMMIT();
        CPAB(2, 2); CP_COMMIT();

        for (int kt4 = 0; kt4 < NK32; kt4 += 4) {
            ITER(kt4 + 0, 0);
            ITER(kt4 + 1, 1);
            ITER(kt4 + 2, 2);
            ITER(kt4 + 3, 3);
        }
#undef CPAB
#undef COMPUTE
#undef ITER

        if (AOUT) {
#pragma unroll
            for (int mt = 0; mt < 4; mt++) {
#pragma unroll
                for (int nt = 0; nt < 4; nt++) {
                    int col = n0 + wn + nt * 8 + qd * 2;
                    float b0 = bias[col], b1 = bias[col + 1];
#pragma unroll
                    for (int h = 0; h < 2; h++) {
                        float v0 = acc[mt][nt][h * 2 + 0] + b0;
                        float v1 = acc[mt][nt][h * 2 + 1] + b1;
                        v0 = 0.5f * v0 * (1.0f + erff(v0 * 0.70710678118654752f));
                        v1 = 0.5f * v1 * (1.0f + erff(v1 * 0.70710678118654752f));
                        size_t row16 = (size_t)((m0 >> 4) + wm16 + mt);
                        int col16 = ((n0 + wn) >> 4) + (nt >> 1);
                        uint32_t* cw = (uint32_t*)Cv + (size_t)e * sC
                                     + (row16 * (ldc >> 4) + col16) * 128
                                     + lane * 4 + 2 * (nt & 1);
                        __half2 hv = __floats2half2_rn(v0, v1);
                        cw[h] = *(uint32_t*)&hv;
                    }
                }
            }
        } else {
            float* C = (float*)Cv + (size_t)e * sC;
#pragma unroll
            for (int mt = 0; mt < 4; mt++) {
#pragma unroll
                for (int nt = 0; nt < 4; nt++) {
                    int col = n0 + wn + nt * 8 + qd * 2;
                    float b0 = bias[col], b1 = bias[col + 1];
#pragma unroll
                    for (int h = 0; h < 2; h++) {
                        float v0 = acc[mt][nt][h * 2 + 0] + b0;
                        float v1 = acc[mt][nt][h * 2 + 1] + b1;
                        size_t row = (size_t)(m0 + (wm16 << 4) + mt * 16 + grp + h * 8);
                        *(float2*)(C + row * ldc + col) = make_float2(v0, v1);
                    }
                }
            }
        }
    }
}

// ---------------- combine ----------------
__global__ void combine_kernel(const int* __restrict__ expid,
                               const int* __restrict__ slot,
                               const float* __restrict__ wt,
                               const float* __restrict__ eout,
                               float* __restrict__ out) {
    int t = blockIdx.x;
    int e0 = expid[t],          s0 = slot[t];          float w0 = wt[t];
    int e1 = expid[N_TOK + t],  s1 = slot[N_TOK + t];  float w1 = wt[N_TOK + t];
    int i = threadIdx.x;
    float4 r = make_float4(0.f, 0.f, 0.f, 0.f);
    if (s0 >= 0) {
        float4 v = ((const float4*)(eout + ((size_t)e0 * CAP + s0) * DIM))[i];
        r.x += w0 * v.x; r.y += w0 * v.y; r.z += w0 * v.z; r.w += w0 * v.w;
    }
    if (s1 >= 0) {
        float4 v = ((const float4*)(eout + ((size_t)e1 * CAP + s1) * DIM))[i];
        r.x += w1 * v.x; r.y += w1 * v.y; r.z += w1 * v.z; r.w += w1 * v.w;
    }
    ((float4*)(out + (size_t)t * DIM))[i] = r;
}

// ---------------- launch ----------------
extern "C" void kernel_launch(void* const* d_in, const int* in_sizes, int n_in,
                              void* d_out, int out_size) {
    const float* x         = (const float*)d_in[0];
    const float* gate_w    = (const float*)d_in[1];
    const float* c_fc      = (const float*)d_in[2];
    const float* fc_bias   = (const float*)d_in[3];
    const float* c_proj    = (const float*)d_in[4];
    const float* proj_bias = (const float*)d_in[5];
    float* out = (float*)d_out;

    uint32_t *xbuf, *hbuf, *wr1, *wr2;
    float *eout, *wt;
    int *expid, *slot, *hist;
    cudaGetSymbolAddress((void**)&xbuf,  g_xbuf);
    cudaGetSymbolAddress((void**)&hbuf,  g_h);
    cudaGetSymbolAddress((void**)&eout,  g_eout);
    cudaGetSymbolAddress((void**)&wr1,   g_wr1);
    cudaGetSymbolAddress((void**)&wr2,   g_wr2);
    cudaGetSymbolAddress((void**)&expid, g_expid);
    cudaGetSymbolAddress((void**)&slot,  g_slot);
    cudaGetSymbolAddress((void**)&hist,  g_hist);
    cudaGetSymbolAddress((void**)&wt,    g_wtp);

    int nsm = 148;
    cudaDeviceGetAttribute(&nsm, cudaDevAttrMultiProcessorCount, 0);
    const int pgrid = 2 * nsm;

    const int smem_bytes = SMEM_W * 4;
    cudaFuncSetAttribute(gemm_fp16<true>,  cudaFuncAttributeMaxDynamicSharedMemorySize, smem_bytes);
    cudaFuncSetAttribute(gemm_fp16<false>, cudaFuncAttributeMaxDynamicSharedMemorySize, smem_bytes);

    // router + permute1 share
    router_kernel<<<N_TOK / 8 + P1_ROUTER, 256>>>(x, gate_w, expid, wt, c_fc, wr1);

    // histograms + permute1 share
    hist_perm_kernel<<<32 + P1_HIST, 256>>>(expid, hist, c_fc, wr1);

    // slots
    slot_kernel<<<32, 256>>>(expid, hist, slot);

    // gather + permute1 share
    gather_kernel<<<2 * N_TOK + P1_GATHER, 256>>>(x, expid, slot, xbuf, c_fc, wr1);

    // GEMM1 + GELU (A'-out) with fused permute2 c_proj -> wr2 interleaved
    const int p2units = (NEXP * (HID / 32) * (DIM / 32)) / 8;   // 4096
    gemm_fp16<true><<<pgrid, 256, smem_bytes>>>(xbuf, wr1, fc_bias, hbuf,
                                                HID,
                                                (long long)CAP * DIM / 2, (long long)DIM * HID / 2,
                                                (long long)CAP * HID / 2, HID,
                                                DIM / 32, HID / 128, CAP / 128,
                                                c_proj, wr2, HID, DIM, p2units);

    // GEMM2 + bias -> eout (fp32 row-major)
    gemm_fp16<false><<<pgrid, 256, smem_bytes>>>(hbuf, wr2, proj_bias, eout,
                                                 DIM,
                                                 (long long)CAP * HID / 2, (long long)HID * DIM / 2,
                                                 (long long)CAP * DIM, DIM,
                                                 HID / 32, DIM / 128, CAP / 128,
                                                 (const float*)nullptr, (uint32_t*)nullptr,
                                                 0, 0, 0);

    combine_kernel<<<N_TOK, 256>>>(expid, slot, wt, eout, out);
}